// round 14
// baseline (speedup 1.0000x reference)
#include <cuda_runtime.h>
#include <cuda_fp16.h>
#include <cstddef>

// Problem dims (fixed): (B=2, C=1, D=160, H=192, W=160) fp32, WIN=9 box, zero pad
#define Bn 2
#define Dn 160
#define Hn 192
#define Wn 160
#define Rr 4
#define HW (Hn*Wn)
#define DHW (Dn*HW)
#define NB (Bn*DHW)          // 9,830,400 outputs
#define NCH 5
#define NQ (Wn/4)            // 40 w-quads

// K1 (fused H-then-W filter)
#define HSPLIT 4
#define HCHUNK (Hn/HSPLIT)   // 48
#define HSUB (HCHUNK/4)      // 12 output rows per thread-substream
#define NROWS 4
#define SROW 42              // padded quad row: [0]=left pad, [41]=right pad

// K2 (D-filter + cc): DSPLIT=10 -> 960 blocks (proven shape, unchanged)
#define DSPLIT 10
#define DCHUNK (Dn/DSPLIT)   // 16
#define NPART (Bn*(Hn/NROWS)*DSPLIT)   // 960

// Scratch TRANSPOSED fp16 with padded D axis, holding WH-filtered sums:
//   [ch][b][h][dp][w],  dp = d + PADLO,  dp in [0, DP)
// Pad planes are NEVER written; __device__ globals are zero-initialized,
// so they are permanently zero -> K2's D loop is branch-free.
#define DP 176
#define PADLO 8
#define NBP ((size_t)Bn*Hn*DP*Wn)      // 10,813,440 els per channel
__device__ uint2 g_buf[NCH * NBP / 4]; // ~108.1 MB, 8B-aligned, zero-init
__device__ double g_part[NPART];
__device__ unsigned int g_done = 0;

__device__ __forceinline__ float4 f4zero() { return make_float4(0.f,0.f,0.f,0.f); }
#define ADD4(S,V) do{ S.x+=V.x; S.y+=V.y; S.z+=V.z; S.w+=V.w; }while(0)
#define SUB4(S,V) do{ S.x-=V.x; S.y-=V.y; S.z-=V.z; S.w-=V.w; }while(0)

// one 8B load -> 4 floats
__device__ __forceinline__ float4 ldh4(const __half* a) {
    const uint2 u = *(const uint2*)a;
    const __half2 h0 = *(const __half2*)&u.x;
    const __half2 h1 = *(const __half2*)&u.y;
    const float2 lo = __half22float2(h0);
    const float2 hi = __half22float2(h1);
    return make_float4(lo.x, lo.y, hi.x, hi.y);
}
// 4 floats -> one 8B store
__device__ __forceinline__ void sth4(__half* a, float4 v) {
    const __half2 h0 = __floats2half2_rn(v.x, v.y);
    const __half2 h1 = __floats2half2_rn(v.z, v.w);
    uint2 u;
    u.x = *(const unsigned*)&h0;
    u.y = *(const unsigned*)&h1;
    *(uint2*)a = u;
}

// 12 consecutive values -> four 9-tap sliding sums
__device__ __forceinline__ float4 slide9(const float v[12]) {
    float s = v[0]+v[1]+v[2]+v[3]+v[4]+v[5]+v[6]+v[7]+v[8];
    float4 o;
    o.x = s; s += v[9]  - v[0];
    o.y = s; s += v[10] - v[1];
    o.z = s; s += v[11] - v[2];
    o.w = s;
    return o;
}

// ---------------------------------------------------------------------------
// K1: fused H-then-W 9-tap box sums (5 stat channels). The H rolling window
// runs on RAW voxels (add row r, subtract row r-8 via L1 reload — exact
// telescoping, ~56 fp ops), so there is NO duplicated W-filter work. The W
// 9-tap is applied once per emitted row via a double-buffered smem stage
// (5 STS.128 + 15 LDS.128 + 5x slide9, one uniform sync). fp16 stores into
// TRANSPOSED padded scratch [ch][b][h][dp][w].
// Block: 160 = 40 quads x 4 h-substreams. Grid: Bn*Dn*HSPLIT = 1280.
// ---------------------------------------------------------------------------
__global__ void __launch_bounds__(160)
pass_hw(const float* __restrict__ I, const float* __restrict__ J,
        __half* __restrict__ out) {
    __shared__ float4 sbuf[2][NROWS][NCH][SROW];

    const int blk = blockIdx.x;
    const int hs  = blk % HSPLIT;
    const int rem = blk / HSPLIT;
    const int d   = rem % Dn;
    const int b   = rem / Dn;

    const int tid  = threadIdx.x;
    const int wq   = tid % NQ;
    const int hsub = tid / NQ;                 // 0..3
    const int hbeg = hs * HCHUNK + hsub * HSUB;

    const size_t pbase = (size_t)b * DHW + (size_t)d * HW + 4*wq;
    const float* bI = I + pbase;
    const float* bJ = J + pbase;
    __half* bO = out + ((size_t)(b*Hn) * DP + (d + PADLO)) * Wn + 4*wq;

    // zero the W pads once (both buffers): 2*4*5*2 = 80 float4s
    for (int i = tid; i < 80; i += 160) {
        const int side = i & 1;
        const int ch   = (i >> 1) % NCH;
        const int rr   = ((i >> 1) / NCH) % NROWS;
        const int bf   = (i >> 1) / (NCH * NROWS);
        sbuf[bf][rr][ch][side ? (SROW-1) : 0] = f4zero();
    }
    __syncthreads();

    // H rolling sums on raw voxels (5 channels x 4 pixels)
    float4 S0=f4zero(), S1=f4zero(), S2=f4zero(), S3=f4zero(), S4=f4zero();

    // k: uniform loop index. r = hbeg + k - 4 (per-substream row).
    // warmup k=0..7 (accumulate only); emit k=8..19 (output o = r-4).
#pragma unroll 4
    for (int k = 0; k < HSUB + 2*Rr; ++k) {
        const int r = hbeg + k - Rr;
        if ((unsigned)r < (unsigned)Hn) {
            const float4 a = *(const float4*)(bI + (size_t)r * Wn);
            const float4 q = *(const float4*)(bJ + (size_t)r * Wn);
            ADD4(S0,a); ADD4(S1,q);
            S2.x += a.x*a.x; S2.y += a.y*a.y; S2.z += a.z*a.z; S2.w += a.w*a.w;
            S3.x += q.x*q.x; S3.y += q.y*q.y; S3.z += q.z*q.z; S3.w += q.w*q.w;
            S4.x += a.x*q.x; S4.y += a.y*q.y; S4.z += a.z*q.z; S4.w += a.w*q.w;
        }

        if (k >= 2*Rr) {                       // uniform across block
            const int o   = r - Rr;            // output row (in [hbeg, hbeg+HSUB))
            const int buf = k & 1;
            sbuf[buf][hsub][0][1+wq] = S0;
            sbuf[buf][hsub][1][1+wq] = S1;
            sbuf[buf][hsub][2][1+wq] = S2;
            sbuf[buf][hsub][3][1+wq] = S3;
            sbuf[buf][hsub][4][1+wq] = S4;
            __syncthreads();

            // W 9-tap from smem (pads give zero boundary)
            float4 W[NCH];
#pragma unroll
            for (int ch = 0; ch < NCH; ++ch) {
                const float4 L = sbuf[buf][hsub][ch][wq];
                const float4 C = sbuf[buf][hsub][ch][1+wq];
                const float4 R = sbuf[buf][hsub][ch][2+wq];
                const float v[12] = {L.x,L.y,L.z,L.w, C.x,C.y,C.z,C.w, R.x,R.y,R.z,R.w};
                W[ch] = slide9(v);
            }

            __half* op = bO + (size_t)o * (DP * Wn);
            sth4(op + 0*NBP, W[0]);
            sth4(op + 1*NBP, W[1]);
            sth4(op + 2*NBP, W[2]);
            sth4(op + 3*NBP, W[3]);
            sth4(op + 4*NBP, W[4]);

            // drop row o-4 = r-8 from the H window (L1-resident raw reload)
            const int qr = r - 2*Rr;
            if (qr >= 0) {
                const float4 a = *(const float4*)(bI + (size_t)qr * Wn);
                const float4 q = *(const float4*)(bJ + (size_t)qr * Wn);
                SUB4(S0,a); SUB4(S1,q);
                S2.x -= a.x*a.x; S2.y -= a.y*a.y; S2.z -= a.z*a.z; S2.w -= a.w*a.w;
                S3.x -= q.x*q.x; S3.y -= q.y*q.y; S3.z -= q.z*q.z; S3.w -= q.w*q.w;
                S4.x -= a.x*q.x; S4.y -= a.y*q.y; S4.z -= a.z*q.z; S4.w -= a.w*q.w;
            }
            // double-buffered: one sync per emitted row suffices
        }
    }
}

// ---------------------------------------------------------------------------
// K2: trivial branch-free D-filter on fp16 WH-sums + cc + global mean.
// (unchanged from R13 — proven 42.5us shape)
// ---------------------------------------------------------------------------
__global__ void __launch_bounds__(160)
pass_d_cc(const __half* __restrict__ in, float* __restrict__ outscalar) {
    const int blk   = blockIdx.x;
    const int chunk = blk % DSPLIT;
    const int id    = blk / DSPLIT;
    const int hg    = id % (Hn/NROWS);
    const int b     = id / (Hn/NROWS);

    const int tid  = threadIdx.x;
    const int wq   = tid % NQ;
    const int row4 = tid / NQ;                 // 0..3
    const int h    = hg * NROWS + row4;

    const __half* pc0 = in + ((size_t)(b*Hn + h) * DP + PADLO) * Wn + 4*wq;
    const __half* pc1 = pc0 + 1*NBP;
    const __half* pc2 = pc0 + 2*NBP;
    const __half* pc3 = pc0 + 3*NBP;
    const __half* pc4 = pc0 + 4*NBP;

    const int o0 = chunk * DCHUNK;

    float4 S0=f4zero(), S1=f4zero(), S2=f4zero(), S3=f4zero(), S4=f4zero();
#pragma unroll
    for (int k = -Rr; k <= Rr; ++k) {
        const ptrdiff_t off = (ptrdiff_t)(o0 + k) * Wn;
        float4 v;
        v = ldh4(pc0 + off); ADD4(S0,v);
        v = ldh4(pc1 + off); ADD4(S1,v);
        v = ldh4(pc2 + off); ADD4(S2,v);
        v = ldh4(pc3 + off); ADD4(S3,v);
        v = ldh4(pc4 + off); ADD4(S4,v);
    }

    const float inv = 1.0f / 729.0f;
    float accf = 0.f;

    for (int o = o0; o < o0 + DCHUNK; ++o) {
        {
            const float mu1=S0.x*inv, mu2=S1.x*inv;
            const float v1=S2.x*inv-mu1*mu1, v2=S3.x*inv-mu2*mu2, cv=S4.x*inv-mu1*mu2;
            accf += __fdividef(cv*cv, v1*v2 + 1e-5f);
        }
        {
            const float mu1=S0.y*inv, mu2=S1.y*inv;
            const float v1=S2.y*inv-mu1*mu1, v2=S3.y*inv-mu2*mu2, cv=S4.y*inv-mu1*mu2;
            accf += __fdividef(cv*cv, v1*v2 + 1e-5f);
        }
        {
            const float mu1=S0.z*inv, mu2=S1.z*inv;
            const float v1=S2.z*inv-mu1*mu1, v2=S3.z*inv-mu2*mu2, cv=S4.z*inv-mu1*mu2;
            accf += __fdividef(cv*cv, v1*v2 + 1e-5f);
        }
        {
            const float mu1=S0.w*inv, mu2=S1.w*inv;
            const float v1=S2.w*inv-mu1*mu1, v2=S3.w*inv-mu2*mu2, cv=S4.w*inv-mu1*mu2;
            accf += __fdividef(cv*cv, v1*v2 + 1e-5f);
        }

        {
            const ptrdiff_t oa = (ptrdiff_t)(o + Rr + 1) * Wn;
            const ptrdiff_t os = (ptrdiff_t)(o - Rr) * Wn;
            float4 v;
            v = ldh4(pc0 + oa); ADD4(S0,v);
            v = ldh4(pc1 + oa); ADD4(S1,v);
            v = ldh4(pc2 + oa); ADD4(S2,v);
            v = ldh4(pc3 + oa); ADD4(S3,v);
            v = ldh4(pc4 + oa); ADD4(S4,v);
            v = ldh4(pc0 + os); SUB4(S0,v);
            v = ldh4(pc1 + os); SUB4(S1,v);
            v = ldh4(pc2 + os); SUB4(S2,v);
            v = ldh4(pc3 + os); SUB4(S3,v);
            v = ldh4(pc4 + os); SUB4(S4,v);
        }
    }

    __shared__ double red[160];
    const int w = tid;
    red[w] = (double)accf;
    __syncthreads();
    if (w < 32) red[w] += red[w + 128];
    __syncthreads();
#pragma unroll
    for (int s = 64; s > 0; s >>= 1) {
        if (w < s) red[w] += red[w + s];
        __syncthreads();
    }

    __shared__ int isLast;
    if (w == 0) {
        g_part[blk] = red[0];
        __threadfence();
        const unsigned v = atomicAdd(&g_done, 1u);
        isLast = (v == (unsigned)(gridDim.x - 1));
    }
    __syncthreads();

    if (isLast) {
        __threadfence();
        double a = 0.0;
        for (int i = w; i < NPART; i += 160) a += g_part[i];  // fixed order
        red[w] = a;
        __syncthreads();
        if (w < 32) red[w] += red[w + 128];
        __syncthreads();
#pragma unroll
        for (int s = 64; s > 0; s >>= 1) {
            if (w < s) red[w] += red[w + s];
            __syncthreads();
        }
        if (w == 0) {
            outscalar[0] = (float)(-red[0] / (double)NB);
            g_done = 0;   // reset for next graph replay
        }
    }
}

extern "C" void kernel_launch(void* const* d_in, const int* in_sizes, int n_in,
                              void* d_out, int out_size) {
    const float* I = (const float*)d_in[0];   // y_true
    const float* J = (const float*)d_in[1];   // y_pred
    float* out = (float*)d_out;

    void* bufraw;
    cudaGetSymbolAddress(&bufraw, g_buf);
    __half* buf = (__half*)bufraw;

    pass_hw<<<Bn * Dn * HSPLIT, 160>>>(I, J, buf);
    pass_d_cc<<<Bn * (Hn/NROWS) * DSPLIT, 160>>>(buf, out);
}

// round 15
// speedup vs baseline: 1.0922x; 1.0922x over previous
#include <cuda_runtime.h>
#include <cuda_fp16.h>
#include <cstddef>

// Problem dims (fixed): (B=2, C=1, D=160, H=192, W=160) fp32, WIN=9 box, zero pad
#define Bn 2
#define Dn 160
#define Hn 192
#define Wn 160
#define Rr 4
#define HW (Hn*Wn)
#define DHW (Dn*HW)
#define NB (Bn*DHW)          // 9,830,400 outputs
#define NCH 5
#define NQ (Wn/4)            // 40 w-quads

// K1 (fused W+H filter): HSPLIT=4 — R12's measured-best K1 shape (52.4us)
#define HSPLIT 4
#define HCHUNK (Hn/HSPLIT)   // 48
#define HSUB (HCHUNK/4)      // 12 output rows per thread

// K2 (D-filter + cc): DSPLIT=10 — R13's measured-best K2 shape (42.1us)
#define DSPLIT 10
#define DCHUNK (Dn/DSPLIT)   // 16
#define NROWS 4
#define NPART (Bn*(Hn/NROWS)*DSPLIT)   // 960

// Scratch TRANSPOSED fp16 with padded D axis, holding WH-filtered sums:
//   [ch][b][h][dp][w],  dp = d + PADLO,  dp in [0, DP)
// Pad planes are NEVER written; __device__ globals are zero-initialized,
// so they are permanently zero -> K2's D loop is branch-free.
#define DP 176
#define PADLO 8
#define NBP ((size_t)Bn*Hn*DP*Wn)      // 10,813,440 els per channel
__device__ uint2 g_buf[NCH * NBP / 4]; // ~108.1 MB, 8B-aligned, zero-init
__device__ double g_part[NPART];
__device__ unsigned int g_done = 0;

__device__ __forceinline__ float4 f4zero() { return make_float4(0.f,0.f,0.f,0.f); }
#define ADD4(S,V) do{ S.x+=V.x; S.y+=V.y; S.z+=V.z; S.w+=V.w; }while(0)
#define SUB4(S,V) do{ S.x-=V.x; S.y-=V.y; S.z-=V.z; S.w-=V.w; }while(0)

// one 8B load -> 4 floats
__device__ __forceinline__ float4 ldh4(const __half* a) {
    const uint2 u = *(const uint2*)a;
    const __half2 h0 = *(const __half2*)&u.x;
    const __half2 h1 = *(const __half2*)&u.y;
    const float2 lo = __half22float2(h0);
    const float2 hi = __half22float2(h1);
    return make_float4(lo.x, lo.y, hi.x, hi.y);
}
// 4 floats -> one 8B store
__device__ __forceinline__ void sth4(__half* a, float4 v) {
    const __half2 h0 = __floats2half2_rn(v.x, v.y);
    const __half2 h1 = __floats2half2_rn(v.z, v.w);
    uint2 u;
    u.x = *(const unsigned*)&h0;
    u.y = *(const unsigned*)&h1;
    *(uint2*)a = u;
}

// 12 consecutive values -> four 9-tap sliding sums
__device__ __forceinline__ float4 slide9(const float v[12]) {
    float s = v[0]+v[1]+v[2]+v[3]+v[4]+v[5]+v[6]+v[7]+v[8];
    float4 o;
    o.x = s; s += v[9]  - v[0];
    o.y = s; s += v[10] - v[1];
    o.z = s; s += v[11] - v[2];
    o.w = s;
    return o;
}

// One raw row's 12-value neighborhood for a w-quad (zero-padded at W edges)
// -> the 5 channel 9-tap W-sums.
__device__ __forceinline__ void row_wsums(const float* __restrict__ rI,
                                          const float* __restrict__ rJ,
                                          int wq,
                                          float4& w0, float4& w1, float4& w2,
                                          float4& w3, float4& w4) {
    const float4 aL = (wq > 0)      ? *(const float4*)(rI - 4) : f4zero();
    const float4 aC =                 *(const float4*)(rI);
    const float4 aR = (wq < NQ - 1) ? *(const float4*)(rI + 4) : f4zero();
    const float4 bL = (wq > 0)      ? *(const float4*)(rJ - 4) : f4zero();
    const float4 bC =                 *(const float4*)(rJ);
    const float4 bR = (wq < NQ - 1) ? *(const float4*)(rJ + 4) : f4zero();

    float x[12] = {aL.x,aL.y,aL.z,aL.w, aC.x,aC.y,aC.z,aC.w, aR.x,aR.y,aR.z,aR.w};
    float y[12] = {bL.x,bL.y,bL.z,bL.w, bC.x,bC.y,bC.z,bC.w, bR.x,bR.y,bR.z,bR.w};

    w0 = slide9(x);
    w1 = slide9(y);
    float t[12];
#pragma unroll
    for (int k = 0; k < 12; ++k) t[k] = x[k]*x[k];
    w2 = slide9(t);
#pragma unroll
    for (int k = 0; k < 12; ++k) t[k] = y[k]*y[k];
    w3 = slide9(t);
#pragma unroll
    for (int k = 0; k < 12; ++k) t[k] = x[k]*y[k];
    w4 = slide9(t);
}

// ---------------------------------------------------------------------------
// K1: fused W+H 9-tap box sums (5 stat channels), fp32 accumulate, no smem,
// no syncs. Rolling H window; subtract side recomputes the leaving row's
// W-sums from L1-resident raw rows (exact telescoping). Stores fp16
// WH-sums into the TRANSPOSED padded scratch [ch][b][h][dp][w].
// Thread = one w-quad, one 12-row h substream. Grid: Bn*Dn*HSPLIT = 1280.
// ---------------------------------------------------------------------------
__global__ void __launch_bounds__(160)
pass_wh(const float* __restrict__ I, const float* __restrict__ J,
        __half* __restrict__ out) {
    const int blk = blockIdx.x;
    const int hs  = blk % HSPLIT;
    const int rem = blk / HSPLIT;
    const int d   = rem % Dn;
    const int b   = rem / Dn;

    const int tid  = threadIdx.x;
    const int wq   = tid % NQ;
    const int hsub = tid / NQ;                 // 0..3
    const int hbeg = hs * HCHUNK + hsub * HSUB;

    const size_t pbase = (size_t)b * DHW + (size_t)d * HW + 4*wq;
    const float* bI = I + pbase;
    const float* bJ = J + pbase;
    // transposed store base: h gets added per output row
    __half* bO = out + ((size_t)(b*Hn) * DP + (d + PADLO)) * Wn + 4*wq;

    float4 S0=f4zero(), S1=f4zero(), S2=f4zero(), S3=f4zero(), S4=f4zero();

    for (int r = hbeg - Rr; r <= hbeg + HSUB + Rr - 1; ++r) {
        if ((unsigned)r < (unsigned)Hn) {
            float4 w0,w1,w2,w3,w4;
            row_wsums(bI + (size_t)r*Wn, bJ + (size_t)r*Wn, wq,
                      w0,w1,w2,w3,w4);
            ADD4(S0,w0); ADD4(S1,w1); ADD4(S2,w2); ADD4(S3,w3); ADD4(S4,w4);
        }
        const int o = r - Rr;
        if (o >= hbeg) {
            __half* op = bO + (size_t)o * (DP * Wn);
            sth4(op + 0*NBP, S0);
            sth4(op + 1*NBP, S1);
            sth4(op + 2*NBP, S2);
            sth4(op + 3*NBP, S3);
            sth4(op + 4*NBP, S4);

            const int qr = r - 2*Rr;           // row leaving the window
            if (qr >= 0) {
                float4 w0,w1,w2,w3,w4;
                row_wsums(bI + (size_t)qr*Wn, bJ + (size_t)qr*Wn, wq,
                          w0,w1,w2,w3,w4);
                SUB4(S0,w0); SUB4(S1,w1); SUB4(S2,w2); SUB4(S3,w3); SUB4(S4,w4);
            }
        }
    }
}

// ---------------------------------------------------------------------------
// K2: trivial branch-free D-filter on fp16 WH-sums + cc + global mean.
// Register rolling window; add streams 320B-stride, subtract reloads are
// L1/L2-resident; pads make everything unconditional. No smem stage, no
// per-plane syncs. Block: 160 = 40 quads x 4 h-rows. Grid: 960.
// ---------------------------------------------------------------------------
__global__ void __launch_bounds__(160)
pass_d_cc(const __half* __restrict__ in, float* __restrict__ outscalar) {
    const int blk   = blockIdx.x;
    const int chunk = blk % DSPLIT;
    const int id    = blk / DSPLIT;
    const int hg    = id % (Hn/NROWS);
    const int b     = id / (Hn/NROWS);

    const int tid  = threadIdx.x;
    const int wq   = tid % NQ;
    const int row4 = tid / NQ;                 // 0..3
    const int h    = hg * NROWS + row4;

    // per-channel base pointers at d=0 for this (b,h,quad)
    const __half* pc0 = in + ((size_t)(b*Hn + h) * DP + PADLO) * Wn + 4*wq;
    const __half* pc1 = pc0 + 1*NBP;
    const __half* pc2 = pc0 + 2*NBP;
    const __half* pc3 = pc0 + 3*NBP;
    const __half* pc4 = pc0 + 4*NBP;

    const int o0 = chunk * DCHUNK;

    // init D window: planes [o0-4 .. o0+4] — pads make this unconditional
    float4 S0=f4zero(), S1=f4zero(), S2=f4zero(), S3=f4zero(), S4=f4zero();
#pragma unroll
    for (int k = -Rr; k <= Rr; ++k) {
        const ptrdiff_t off = (ptrdiff_t)(o0 + k) * Wn;
        float4 v;
        v = ldh4(pc0 + off); ADD4(S0,v);
        v = ldh4(pc1 + off); ADD4(S1,v);
        v = ldh4(pc2 + off); ADD4(S2,v);
        v = ldh4(pc3 + off); ADD4(S3,v);
        v = ldh4(pc4 + off); ADD4(S4,v);
    }

    const float inv = 1.0f / 729.0f;
    float accf = 0.f;

    for (int o = o0; o < o0 + DCHUNK; ++o) {
        // cc epilogue on current window [o-4, o+4]
        {
            const float mu1=S0.x*inv, mu2=S1.x*inv;
            const float v1=S2.x*inv-mu1*mu1, v2=S3.x*inv-mu2*mu2, cv=S4.x*inv-mu1*mu2;
            accf += __fdividef(cv*cv, v1*v2 + 1e-5f);
        }
        {
            const float mu1=S0.y*inv, mu2=S1.y*inv;
            const float v1=S2.y*inv-mu1*mu1, v2=S3.y*inv-mu2*mu2, cv=S4.y*inv-mu1*mu2;
            accf += __fdividef(cv*cv, v1*v2 + 1e-5f);
        }
        {
            const float mu1=S0.z*inv, mu2=S1.z*inv;
            const float v1=S2.z*inv-mu1*mu1, v2=S3.z*inv-mu2*mu2, cv=S4.z*inv-mu1*mu2;
            accf += __fdividef(cv*cv, v1*v2 + 1e-5f);
        }
        {
            const float mu1=S0.w*inv, mu2=S1.w*inv;
            const float v1=S2.w*inv-mu1*mu1, v2=S3.w*inv-mu2*mu2, cv=S4.w*inv-mu1*mu2;
            accf += __fdividef(cv*cv, v1*v2 + 1e-5f);
        }

        // branch-free advance: add plane o+5, drop plane o-4 (pads = zero)
        {
            const ptrdiff_t oa = (ptrdiff_t)(o + Rr + 1) * Wn;
            const ptrdiff_t os = (ptrdiff_t)(o - Rr) * Wn;
            float4 v;
            v = ldh4(pc0 + oa); ADD4(S0,v);
            v = ldh4(pc1 + oa); ADD4(S1,v);
            v = ldh4(pc2 + oa); ADD4(S2,v);
            v = ldh4(pc3 + oa); ADD4(S3,v);
            v = ldh4(pc4 + oa); ADD4(S4,v);
            v = ldh4(pc0 + os); SUB4(S0,v);
            v = ldh4(pc1 + os); SUB4(S1,v);
            v = ldh4(pc2 + os); SUB4(S2,v);
            v = ldh4(pc3 + os); SUB4(S3,v);
            v = ldh4(pc4 + os); SUB4(S4,v);
        }
    }

    // Deterministic block reduction (160 -> 1)
    __shared__ double red[160];
    const int w = tid;
    red[w] = (double)accf;
    __syncthreads();
    if (w < 32) red[w] += red[w + 128];
    __syncthreads();
#pragma unroll
    for (int s = 64; s > 0; s >>= 1) {
        if (w < s) red[w] += red[w + s];
        __syncthreads();
    }

    __shared__ int isLast;
    if (w == 0) {
        g_part[blk] = red[0];
        __threadfence();
        const unsigned v = atomicAdd(&g_done, 1u);
        isLast = (v == (unsigned)(gridDim.x - 1));
    }
    __syncthreads();

    if (isLast) {
        __threadfence();
        double a = 0.0;
        for (int i = w; i < NPART; i += 160) a += g_part[i];  // fixed order
        red[w] = a;
        __syncthreads();
        if (w < 32) red[w] += red[w + 128];
        __syncthreads();
#pragma unroll
        for (int s = 64; s > 0; s >>= 1) {
            if (w < s) red[w] += red[w + s];
            __syncthreads();
        }
        if (w == 0) {
            outscalar[0] = (float)(-red[0] / (double)NB);
            g_done = 0;   // reset for next graph replay
        }
    }
}

extern "C" void kernel_launch(void* const* d_in, const int* in_sizes, int n_in,
                              void* d_out, int out_size) {
    const float* I = (const float*)d_in[0];   // y_true
    const float* J = (const float*)d_in[1];   // y_pred
    float* out = (float*)d_out;

    void* bufraw;
    cudaGetSymbolAddress(&bufraw, g_buf);
    __half* buf = (__half*)bufraw;

    pass_wh<<<Bn * Dn * HSPLIT, 160>>>(I, J, buf);
    pass_d_cc<<<Bn * (Hn/NROWS) * DSPLIT, 160>>>(buf, out);
}